// round 4
// baseline (speedup 1.0000x reference)
#include <cuda_runtime.h>
#include <cuda_bf16.h>

// Problem dims (fixed by the dataset)
#define LSEQ 512
#define DIN  320
#define HID  512
#define G4   2048   // 4*H
#define MDIM 512

// ---------------- scratch (static device globals; no allocation) ----------
__device__ float g_x0 [LSEQ * DIN];        // embeddings
__device__ float g_x1 [LSEQ * 2 * HID];    // layer0 output (fwd 0..511, bwd 512..1023)
__device__ float g_x2 [LSEQ * 2 * HID];    // layer1 output
__device__ float g_zf [LSEQ * G4];         // input-projection, forward dir
__device__ float g_zb [LSEQ * G4];         // input-projection, backward dir
__device__ float g_mlp[LSEQ * MDIM];       // per-node MLP
// per-(layer,dir,block) publish flags, one 128B line each: [2][128][32]
__device__ unsigned int g_flag[2 * 128 * 32];

__device__ __forceinline__ float* bufsel(int id) {
    switch (id) {
        case 0: return g_x0;
        case 1: return g_x1;
        case 2: return g_x2;
        case 3: return g_zf;
        case 4: return g_zb;
        default: return g_mlp;
    }
}

__device__ __forceinline__ float tanh_f(float x) {
    float a = fabsf(x);
    float e = __expf(-2.0f * a);
    float r = __fdividef(1.0f - e, 1.0f + e);
    return copysignf(r, x);
}

__device__ __forceinline__ void st_release_u32(unsigned int* p, unsigned int v) {
    asm volatile("st.release.gpu.global.u32 [%0], %1;" :: "l"(p), "r"(v) : "memory");
}
__device__ __forceinline__ unsigned int ld_acquire_u32(const unsigned int* p) {
    unsigned int v;
    asm volatile("ld.acquire.gpu.global.u32 %0, [%1];" : "=r"(v) : "l"(p) : "memory");
    return v;
}
__device__ __forceinline__ uint4 ldcg_v4(const uint4* p) {
    uint4 v;
    asm volatile("ld.global.cg.v4.u32 {%0,%1,%2,%3}, [%4];"
                 : "=r"(v.x), "=r"(v.y), "=r"(v.z), "=r"(v.w) : "l"(p) : "memory");
    return v;
}

// ---------------- embedding gather ----------------------------------------
__global__ void embed_k(const int* __restrict__ wi, const int* __restrict__ pi,
                        const float* __restrict__ we, const float* __restrict__ pe)
{
    int t = blockIdx.x;
    int d = threadIdx.x;             // 320 threads
    float v;
    if (d < 256) v = we[(size_t)wi[t] * 256 + d];
    else         v = pe[(size_t)pi[t] * 64 + (d - 256)];
    g_x0[t * DIN + d] = v;
}

// ---------------- flag reset (every replay, before the scans) -------------
__global__ void zero_flags_k()
{
    g_flag[blockIdx.x * 1024 + threadIdx.x] = 0u;   // 8 blocks x 1024 = 8192
}

// ---------------- f32 GEMM:  C[M,N] = A[M,K] * B[N,K]^T + b1 + b2 ---------
__global__ void __launch_bounds__(256) gemm_tn(
    int aid,
    const float* __restrict__ B0, const float* __restrict__ b1_0,
    const float* __restrict__ b2_0, int cid0,
    const float* __restrict__ B1, const float* __restrict__ b1_1,
    const float* __restrict__ b2_1, int cid1,
    int M, int N, int K)
{
    const float* A  = bufsel(aid);
    const float* B  = blockIdx.z ? B1   : B0;
    const float* b1 = blockIdx.z ? b1_1 : b1_0;
    const float* b2 = blockIdx.z ? b2_1 : b2_0;
    float*       C  = bufsel(blockIdx.z ? cid1 : cid0);

    __shared__ float As[16][65];
    __shared__ float Bs[16][65];

    const int tid = threadIdx.x;
    const int tx  = tid & 15;
    const int ty  = tid >> 4;
    const int m0  = blockIdx.y * 64;
    const int n0  = blockIdx.x * 64;

    const int lr = tid >> 2;
    const int lk = (tid & 3) * 4;

    const float* Ap = A + (size_t)(m0 + lr) * K + lk;
    const float* Bp = B + (size_t)(n0 + lr) * K + lk;

    float acc[4][4] = {};

    for (int k0 = 0; k0 < K; k0 += 16) {
        float4 av = *(const float4*)(Ap + k0);
        float4 bv = *(const float4*)(Bp + k0);
        __syncthreads();
        As[lk + 0][lr] = av.x; As[lk + 1][lr] = av.y;
        As[lk + 2][lr] = av.z; As[lk + 3][lr] = av.w;
        Bs[lk + 0][lr] = bv.x; Bs[lk + 1][lr] = bv.y;
        Bs[lk + 2][lr] = bv.z; Bs[lk + 3][lr] = bv.w;
        __syncthreads();
#pragma unroll
        for (int kk = 0; kk < 16; kk++) {
            float a[4], b[4];
#pragma unroll
            for (int i = 0; i < 4; i++) a[i] = As[kk][ty + 16 * i];
#pragma unroll
            for (int j = 0; j < 4; j++) b[j] = Bs[kk][tx + 16 * j];
#pragma unroll
            for (int i = 0; i < 4; i++)
#pragma unroll
                for (int j = 0; j < 4; j++)
                    acc[i][j] += a[i] * b[j];
        }
    }

#pragma unroll
    for (int j = 0; j < 4; j++) {
        int n = n0 + tx + 16 * j;
        float bb = 0.0f;
        if (b1) bb += b1[n];
        if (b2) bb += b2[n];
#pragma unroll
        for (int i = 0; i < 4; i++) {
            C[(size_t)(m0 + ty + 16 * i) * N + n] = acc[i][j] + bb;
        }
    }
}

// ---------------- persistent bidirectional LSTM scan ----------------------
// 128 blocks x 256 threads; blocks 0..63 fwd, 64..127 bwd. Each block owns 8
// hidden units (32 W_hh rows register-resident, packed f32x2).
// Publish: 8 h STGs -> syncwarp -> lane0 st.release flag(=t+1) on own line.
// Consume: 64 threads acquire-poll their producer's flag (>=), then ld.cg.v4
// the 32B chunk into smem. No atomics anywhere.
__global__ void __launch_bounds__(256, 1) lstm_scan(
    const float* __restrict__ whf, const float* __restrict__ whb,
    int outid, int layer)
{
    const int dir = blockIdx.x >> 6;     // 0 fwd, 1 bwd
    const int blk = blockIdx.x & 63;
    const int tid = threadIdx.x;
    const int row = tid >> 3;            // 0..31 local row
    const int sub = tid & 7;             // 8 threads per row
    const int grow = (row >> 3) * HID + blk * 8 + (row & 7);

    const float* zin = dir ? g_zb : g_zf;
    const float* Whh = dir ? whb : whf;
    float* xout = bufsel(outid);
    unsigned int* flags = g_flag + layer * 4096 + dir * 2048;  // [64][32]

    // register-resident W_hh slice, packed as f32x2
    unsigned long long wp[32];
    const unsigned long long* w2 =
        (const unsigned long long*)(Whh + (size_t)grow * HID);
#pragma unroll
    for (int k = 0; k < 32; k++) wp[k] = w2[sub + 8 * k];

    __shared__ __align__(16) float hs[HID];
    __shared__ float zs[32];
    hs[tid] = 0.0f; hs[tid + 256] = 0.0f;
    float c = 0.0f;                      // live only on lanes 0..7 of warp 0
    __syncthreads();

    for (int t = 0; t < LSEQ; t++) {
        const int ta = dir ? (LSEQ - 1 - t) : t;

        // prefetch input-projection term for this step (warp0, 32 lanes)
        float zp = 0.0f;
        if (tid < 32)
            zp = __ldg(zin + (size_t)ta * G4 + (tid >> 3) * HID + blk * 8 + (tid & 7));

        // GEMV partial: 32 x (LDS.64 + FFMA2) per thread
        unsigned long long acc0 = 0ull, acc1 = 0ull;
#pragma unroll
        for (int k = 0; k < 32; k += 2) {
            unsigned long long h0 = *(const unsigned long long*)(hs + 2 * (sub + 8 * k));
            unsigned long long h1 = *(const unsigned long long*)(hs + 2 * (sub + 8 * (k + 1)));
            asm("fma.rn.f32x2 %0, %1, %2, %0;" : "+l"(acc0) : "l"(wp[k]),     "l"(h0));
            asm("fma.rn.f32x2 %0, %1, %2, %0;" : "+l"(acc1) : "l"(wp[k + 1]), "l"(h1));
        }
        float ax, ay, bx, by;
        asm("mov.b64 {%0,%1}, %2;" : "=f"(ax), "=f"(ay) : "l"(acc0));
        asm("mov.b64 {%0,%1}, %2;" : "=f"(bx), "=f"(by) : "l"(acc1));
        float acc = (ax + ay) + (bx + by);
        acc += __shfl_down_sync(0xffffffffu, acc, 4, 8);
        acc += __shfl_down_sync(0xffffffffu, acc, 2, 8);
        acc += __shfl_down_sync(0xffffffffu, acc, 1, 8);
        if (sub == 0) zs[row] = acc;
        __syncthreads();

        // gates: one transcendental per lane (warp 0, 32 lanes)
        if (tid < 32) {
            const int gate = tid >> 3;               // 0=i 1=f 2=g 3=o
            float z = zp + zs[tid];
            float arg = (gate == 2) ? z : 0.5f * z;
            float tv = tanh_f(arg);
            float val = (gate == 2) ? tv : 0.5f + 0.5f * tv;   // sigm via tanh
            float fg = __shfl_sync(0xffffffffu, val, tid + 8);
            float gg = __shfl_sync(0xffffffffu, val, tid + 16);
            float og = __shfl_sync(0xffffffffu, val, tid + 24);
            if (tid < 8) {
                c = fg * c + val * gg;
                float h = og * tanh_f(c);
                xout[(size_t)ta * (2 * HID) + dir * HID + blk * 8 + tid] = h;
                hs[blk * 8 + tid] = h;               // own chunk direct to smem
            }
            __syncwarp(0xffffffffu);
            if (tid == 0 && t < LSEQ - 1)
                st_release_u32(flags + blk * 32, (unsigned int)(t + 1));
        }

        // consume h_t: 64 threads poll per-producer flags, reload chunks
        if (t < LSEQ - 1) {
            if (tid < 64 && tid != blk) {
                const unsigned int* fp = flags + tid * 32;
                while (ld_acquire_u32(fp) < (unsigned int)(t + 1)) { }
                const uint4* p = (const uint4*)(xout + (size_t)ta * (2 * HID)
                                                + dir * HID) + 2 * tid;
                uint4 a = ldcg_v4(p);
                uint4 b = ldcg_v4(p + 1);
                uint4* hd = (uint4*)hs + 2 * tid;
                hd[0] = a; hd[1] = b;
            }
            __syncthreads();
        }
    }
}

// ---------------- pairwise scores ------------------------------------------
__global__ void __launch_bounds__(256) pair_scores(
    const float* __restrict__ ow, const float* __restrict__ obp,
    float* __restrict__ out)
{
    __shared__ float miT[64][33];
    __shared__ float mjT[64][33];
    __shared__ float wch[64];

    const int tid = threadIdx.x;
    const int tx  = tid & 31;
    const int ty  = tid >> 5;            // 0..7
    const int i0  = blockIdx.y * 32;
    const int j0  = blockIdx.x * 32;

    float acc[4] = {0.f, 0.f, 0.f, 0.f};

    for (int mc = 0; mc < MDIM; mc += 64) {
        __syncthreads();
#pragma unroll
        for (int rep = 0; rep < 8; rep++) {
            int idx  = tid + rep * 256;
            int r    = idx >> 6;
            int cidx = idx & 63;
            miT[cidx][r] = g_mlp[(size_t)(i0 + r) * MDIM + mc + cidx];
            int jrow = j0 + r + 1;
            mjT[cidx][r] = (jrow < LSEQ)
                         ? g_mlp[(size_t)jrow * MDIM + mc + cidx] : 0.0f;
        }
        if (tid < 64) wch[tid] = ow[mc + tid];
        __syncthreads();

#pragma unroll 4
        for (int cc = 0; cc < 64; cc++) {
            float jv = mjT[cc][tx];
            float wv = wch[cc];
#pragma unroll
            for (int ii = 0; ii < 4; ii++) {
                float v = miT[cc][ty + 8 * ii] + jv;
                acc[ii] += tanh_f(v) * wv;
            }
        }
    }

    float ob = obp[0];
    int j = j0 + tx;
    if (j < LSEQ - 1) {
#pragma unroll
        for (int ii = 0; ii < 4; ii++) {
            int i = i0 + ty + 8 * ii;
            out[(size_t)i * (LSEQ - 1) + j] = acc[ii] + ob;
        }
    }
}

// ---------------- launch ----------------------------------------------------
extern "C" void kernel_launch(void* const* d_in, const int* in_sizes, int n_in,
                              void* d_out, int out_size)
{
    const int*   wi    = (const int*)  d_in[0];
    const int*   pi    = (const int*)  d_in[1];
    const float* we    = (const float*)d_in[2];
    const float* pe    = (const float*)d_in[3];
    const float* Wih0  = (const float*)d_in[4];
    const float* Whh0  = (const float*)d_in[5];
    const float* bih0  = (const float*)d_in[6];
    const float* bhh0  = (const float*)d_in[7];
    const float* Wih0r = (const float*)d_in[8];
    const float* Whh0r = (const float*)d_in[9];
    const float* bih0r = (const float*)d_in[10];
    const float* bhh0r = (const float*)d_in[11];
    const float* Wih1  = (const float*)d_in[12];
    const float* Whh1  = (const float*)d_in[13];
    const float* bih1  = (const float*)d_in[14];
    const float* bhh1  = (const float*)d_in[15];
    const float* Wih1r = (const float*)d_in[16];
    const float* Whh1r = (const float*)d_in[17];
    const float* bih1r = (const float*)d_in[18];
    const float* bhh1r = (const float*)d_in[19];
    const float* mlpW  = (const float*)d_in[20];
    const float* mlpb  = (const float*)d_in[21];
    const float* outw  = (const float*)d_in[22];
    const float* outb  = (const float*)d_in[23];

    embed_k<<<LSEQ, DIN>>>(wi, pi, we, pe);
    zero_flags_k<<<8, 1024>>>();

    // layer 0 input projections (both directions, one launch)
    gemm_tn<<<dim3(G4 / 64, LSEQ / 64, 2), 256>>>(
        0, Wih0, bih0, bhh0, 3, Wih0r, bih0r, bhh0r, 4, LSEQ, G4, DIN);
    lstm_scan<<<128, 256>>>(Whh0, Whh0r, 1, 0);

    // layer 1 input projections
    gemm_tn<<<dim3(G4 / 64, LSEQ / 64, 2), 256>>>(
        1, Wih1, bih1, bhh1, 3, Wih1r, bih1r, bhh1r, 4, LSEQ, G4, 2 * HID);
    lstm_scan<<<128, 256>>>(Whh1, Whh1r, 2, 1);

    // MLP projection
    gemm_tn<<<dim3(MDIM / 64, LSEQ / 64, 1), 256>>>(
        2, mlpW, mlpb, nullptr, 5, mlpW, mlpb, nullptr, 5, LSEQ, MDIM, 2 * HID);
    // pairwise scores
    pair_scores<<<dim3(16, 16), 256>>>(outw, outb, (float*)d_out);
}

// round 5
// speedup vs baseline: 1.0568x; 1.0568x over previous
#include <cuda_runtime.h>
#include <cuda_bf16.h>

// Problem dims (fixed by the dataset)
#define LSEQ 512
#define DIN  320
#define HID  512
#define G4   2048   // 4*H
#define MDIM 512
#define NBLK 32     // blocks per direction
#define UPB  16     // hidden units per block

// ---------------- scratch (static device globals; no allocation) ----------
__device__ float g_x0 [LSEQ * DIN];        // embeddings
__device__ float g_zf [LSEQ * G4];         // input-projection, forward dir
__device__ float g_zb [LSEQ * G4];         // input-projection, backward dir
__device__ float g_mlp[LSEQ * MDIM];       // per-node MLP
// layer outputs in "publish line" layout: [dir][t][blk][32]
//   floats 0..15 = h chunk, word 16 = flag, rest pad (one 128B line)
__device__ __align__(128) float g_pub1[2 * LSEQ * NBLK * 32];
__device__ __align__(128) float g_pub2[2 * LSEQ * NBLK * 32];

__device__ __forceinline__ float* bufsel(int id) {
    switch (id) {
        case 0: return g_x0;
        case 3: return g_zf;
        case 4: return g_zb;
        case 5: return g_mlp;
        case 6: return g_pub1;
        default: return g_pub2;
    }
}

__device__ __forceinline__ float tanh_f(float x) {
    float a = fabsf(x);
    float e = __expf(-2.0f * a);
    float r = __fdividef(1.0f - e, 1.0f + e);
    return copysignf(r, x);
}

__device__ __forceinline__ void st_release_u32(unsigned int* p, unsigned int v) {
    asm volatile("st.release.gpu.global.u32 [%0], %1;" :: "l"(p), "r"(v) : "memory");
}
__device__ __forceinline__ unsigned int ld_acquire_u32(const unsigned int* p) {
    unsigned int v;
    asm volatile("ld.acquire.gpu.global.u32 %0, [%1];" : "=r"(v) : "l"(p) : "memory");
    return v;
}
__device__ __forceinline__ uint4 ldcg_v4(const uint4* p) {
    uint4 v;
    asm volatile("ld.global.cg.v4.u32 {%0,%1,%2,%3}, [%4];"
                 : "=r"(v.x), "=r"(v.y), "=r"(v.z), "=r"(v.w) : "l"(p) : "memory");
    return v;
}

// ---------------- embedding gather ----------------------------------------
__global__ void embed_k(const int* __restrict__ wi, const int* __restrict__ pi,
                        const float* __restrict__ we, const float* __restrict__ pe)
{
    int t = blockIdx.x;
    int d = threadIdx.x;             // 320 threads
    float v;
    if (d < 256) v = we[(size_t)wi[t] * 256 + d];
    else         v = pe[(size_t)pi[t] * 64 + (d - 256)];
    g_x0[t * DIN + d] = v;
}

// ---------------- pub reset (every replay, before the scans) --------------
__global__ void zero_pub_k()
{
    int idx = blockIdx.x * blockDim.x + threadIdx.x;   // 512*512 = 262144
    uint4 z = make_uint4(0u, 0u, 0u, 0u);
    ((uint4*)g_pub1)[idx] = z;                          // 262144 uint4 = 4MB
    ((uint4*)g_pub2)[idx] = z;
}

// ---------------- f32 GEMM:  C[M,N] = A[M,K] * B[N,K]^T + b1 + b2 ---------
// amode=0: A dense [M][K].  amode=1: A in pub-line layout (K=1024,
// col c -> pub[(c>>9)][row][(c>>4)&31][c&15]).
__global__ void __launch_bounds__(256) gemm_tn(
    int aid, int amode,
    const float* __restrict__ B0, const float* __restrict__ b1_0,
    const float* __restrict__ b2_0, int cid0,
    const float* __restrict__ B1, const float* __restrict__ b1_1,
    const float* __restrict__ b2_1, int cid1,
    int M, int N, int K)
{
    const float* A  = bufsel(aid);
    const float* B  = blockIdx.z ? B1   : B0;
    const float* b1 = blockIdx.z ? b1_1 : b1_0;
    const float* b2 = blockIdx.z ? b2_1 : b2_0;
    float*       C  = bufsel(blockIdx.z ? cid1 : cid0);

    __shared__ float As[16][65];
    __shared__ float Bs[16][65];

    const int tid = threadIdx.x;
    const int tx  = tid & 15;
    const int ty  = tid >> 4;
    const int m0  = blockIdx.y * 64;
    const int n0  = blockIdx.x * 64;

    const int lr = tid >> 2;
    const int lk = (tid & 3) * 4;

    const float* Ap = amode ? (A + (size_t)(m0 + lr) * 1024 + lk)
                            : (A + (size_t)(m0 + lr) * K + lk);
    const float* Bp = B + (size_t)(n0 + lr) * K + lk;

    float acc[4][4] = {};

    for (int k0 = 0; k0 < K; k0 += 16) {
        float4 av;
        if (amode) {
            int q = k0 >> 4;                       // 0..63
            av = *(const float4*)(Ap + (q >> 5) * 524288 + (q & 31) * 32);
        } else {
            av = *(const float4*)(Ap + k0);
        }
        float4 bv = *(const float4*)(Bp + k0);
        __syncthreads();
        As[lk + 0][lr] = av.x; As[lk + 1][lr] = av.y;
        As[lk + 2][lr] = av.z; As[lk + 3][lr] = av.w;
        Bs[lk + 0][lr] = bv.x; Bs[lk + 1][lr] = bv.y;
        Bs[lk + 2][lr] = bv.z; Bs[lk + 3][lr] = bv.w;
        __syncthreads();
#pragma unroll
        for (int kk = 0; kk < 16; kk++) {
            float a[4], b[4];
#pragma unroll
            for (int i = 0; i < 4; i++) a[i] = As[kk][ty + 16 * i];
#pragma unroll
            for (int j = 0; j < 4; j++) b[j] = Bs[kk][tx + 16 * j];
#pragma unroll
            for (int i = 0; i < 4; i++)
#pragma unroll
                for (int j = 0; j < 4; j++)
                    acc[i][j] += a[i] * b[j];
        }
    }

#pragma unroll
    for (int j = 0; j < 4; j++) {
        int n = n0 + tx + 16 * j;
        float bb = 0.0f;
        if (b1) bb += b1[n];
        if (b2) bb += b2[n];
#pragma unroll
        for (int i = 0; i < 4; i++) {
            C[(size_t)(m0 + ty + 16 * i) * N + n] = acc[i][j] + bb;
        }
    }
}

// ---------------- persistent bidirectional LSTM scan ----------------------
// 64 blocks x 256 threads; blocks 0..31 fwd, 32..63 bwd. Each block owns 16
// hidden units (64 W_hh rows register-resident, packed f32x2).
// Publish: 16 h floats + flag into ONE 128B line (unique per step).
// Consume: warp 2 (31 pollers) acquire-polls flag !=0 with nanosleep backoff,
// then ld.cg.v4 the 64B chunk into smem.
__global__ void __launch_bounds__(256, 1) lstm_scan(
    const float* __restrict__ whf, const float* __restrict__ whb, int outid)
{
    const int dir = blockIdx.x >> 5;     // 0 fwd, 1 bwd
    const int blk = blockIdx.x & 31;
    const int tid = threadIdx.x;
    const int row = tid >> 2;            // 0..63 local row
    const int sub = tid & 3;             // 4 threads per row
    const int grow = (row >> 4) * HID + blk * UPB + (row & 15);

    const float* zin = dir ? g_zb : g_zf;
    const float* Whh = dir ? whb : whf;
    float* pub = bufsel(outid) + (size_t)dir * LSEQ * NBLK * 32;

    // register-resident W_hh slice, packed as f32x2 (128 regs)
    unsigned long long wp[64];
    const unsigned long long* w2 =
        (const unsigned long long*)(Whh + (size_t)grow * HID);
#pragma unroll
    for (int k = 0; k < 64; k++) wp[k] = w2[sub + 4 * k];

    __shared__ __align__(16) float hs[HID];
    __shared__ float zs[64];
    __shared__ float vals[64];
    hs[tid] = 0.0f; hs[tid + 256] = 0.0f;
    float c = 0.0f;                      // live only on lanes 0..15 of warp 0
    __syncthreads();

    for (int t = 0; t < LSEQ; t++) {
        const int ta = dir ? (LSEQ - 1 - t) : t;

        // prefetch input-projection term for this step (64 gate lanes)
        float zp = 0.0f;
        if (tid < 64)
            zp = __ldg(zin + (size_t)ta * G4 + (tid >> 4) * HID
                       + blk * UPB + (tid & 15));

        // GEMV partial: 64 x (LDS.64 + FFMA2) per thread
        unsigned long long acc0 = 0ull, acc1 = 0ull;
#pragma unroll
        for (int k = 0; k < 64; k += 2) {
            unsigned long long h0 = *(const unsigned long long*)(hs + 2 * (sub + 4 * k));
            unsigned long long h1 = *(const unsigned long long*)(hs + 2 * (sub + 4 * (k + 1)));
            asm("fma.rn.f32x2 %0, %1, %2, %0;" : "+l"(acc0) : "l"(wp[k]),     "l"(h0));
            asm("fma.rn.f32x2 %0, %1, %2, %0;" : "+l"(acc1) : "l"(wp[k + 1]), "l"(h1));
        }
        float ax, ay, bx, by;
        asm("mov.b64 {%0,%1}, %2;" : "=f"(ax), "=f"(ay) : "l"(acc0));
        asm("mov.b64 {%0,%1}, %2;" : "=f"(bx), "=f"(by) : "l"(acc1));
        float acc = (ax + ay) + (bx + by);
        acc += __shfl_down_sync(0xffffffffu, acc, 2, 4);
        acc += __shfl_down_sync(0xffffffffu, acc, 1, 4);
        if (sub == 0) zs[row] = acc;
        __syncthreads();

        // gates: 64 lanes, one transcendental each (warps 0-1)
        if (tid < 64) {
            const int gate = tid >> 4;               // 0=i 1=f 2=g 3=o
            float z = zp + zs[tid];
            float arg = (gate == 2) ? z : 0.5f * z;
            float tv = tanh_f(arg);
            vals[tid] = (gate == 2) ? tv : 0.5f + 0.5f * tv;   // sigm via tanh
            asm volatile("bar.sync 1, 64;" ::: "memory");
        }
        if (tid < 32) {
            if (tid < 16) {
                float ig = vals[tid];
                float fg = vals[16 + tid];
                float gg = vals[32 + tid];
                float og = vals[48 + tid];
                c = fg * c + ig * gg;
                float h = og * tanh_f(c);
                float* line = pub + ((size_t)ta * NBLK + blk) * 32;
                line[tid] = h;                       // publish
                hs[blk * UPB + tid] = h;             // own chunk direct to smem
            }
            __syncwarp(0xffffffffu);
            if (tid == 0)
                st_release_u32((unsigned int*)(pub + ((size_t)ta * NBLK + blk) * 32 + 16), 1u);
        }

        // consume h_t: warp 2 polls 31 remote lines, reloads 64B chunks
        if (t < LSEQ - 1) {
            if (tid >= 64 && tid < 96) {
                int cch = tid - 64;
                if (cch != blk) {
                    const float* line = pub + ((size_t)ta * NBLK + cch) * 32;
                    const unsigned int* fp = (const unsigned int*)(line + 16);
                    if (ld_acquire_u32(fp) == 0u) {
                        for (;;) {
                            __nanosleep(40);
                            if (ld_acquire_u32(fp) != 0u) break;
                        }
                    }
                    const uint4* p = (const uint4*)line;
                    uint4 a = ldcg_v4(p);
                    uint4 b = ldcg_v4(p + 1);
                    uint4 cc = ldcg_v4(p + 2);
                    uint4 d = ldcg_v4(p + 3);
                    uint4* hd = (uint4*)(hs + cch * UPB);
                    hd[0] = a; hd[1] = b; hd[2] = cc; hd[3] = d;
                }
            }
        }
        __syncthreads();
    }
}

// ---------------- pairwise scores ------------------------------------------
__global__ void __launch_bounds__(256) pair_scores(
    const float* __restrict__ ow, const float* __restrict__ obp,
    float* __restrict__ out)
{
    __shared__ float miT[64][33];
    __shared__ float mjT[64][33];
    __shared__ float wch[64];

    const int tid = threadIdx.x;
    const int tx  = tid & 31;
    const int ty  = tid >> 5;            // 0..7
    const int i0  = blockIdx.y * 32;
    const int j0  = blockIdx.x * 32;

    float acc[4] = {0.f, 0.f, 0.f, 0.f};

    for (int mc = 0; mc < MDIM; mc += 64) {
        __syncthreads();
#pragma unroll
        for (int rep = 0; rep < 8; rep++) {
            int idx  = tid + rep * 256;
            int r    = idx >> 6;
            int cidx = idx & 63;
            miT[cidx][r] = g_mlp[(size_t)(i0 + r) * MDIM + mc + cidx];
            int jrow = j0 + r + 1;
            mjT[cidx][r] = (jrow < LSEQ)
                         ? g_mlp[(size_t)jrow * MDIM + mc + cidx] : 0.0f;
        }
        if (tid < 64) wch[tid] = ow[mc + tid];
        __syncthreads();

#pragma unroll 4
        for (int cc = 0; cc < 64; cc++) {
            float jv = mjT[cc][tx];
            float wv = wch[cc];
#pragma unroll
            for (int ii = 0; ii < 4; ii++) {
                float v = miT[cc][ty + 8 * ii] + jv;
                acc[ii] += tanh_f(v) * wv;
            }
        }
    }

    float ob = obp[0];
    int j = j0 + tx;
    if (j < LSEQ - 1) {
#pragma unroll
        for (int ii = 0; ii < 4; ii++) {
            int i = i0 + ty + 8 * ii;
            out[(size_t)i * (LSEQ - 1) + j] = acc[ii] + ob;
        }
    }
}

// ---------------- launch ----------------------------------------------------
extern "C" void kernel_launch(void* const* d_in, const int* in_sizes, int n_in,
                              void* d_out, int out_size)
{
    const int*   wi    = (const int*)  d_in[0];
    const int*   pi    = (const int*)  d_in[1];
    const float* we    = (const float*)d_in[2];
    const float* pe    = (const float*)d_in[3];
    const float* Wih0  = (const float*)d_in[4];
    const float* Whh0  = (const float*)d_in[5];
    const float* bih0  = (const float*)d_in[6];
    const float* bhh0  = (const float*)d_in[7];
    const float* Wih0r = (const float*)d_in[8];
    const float* Whh0r = (const float*)d_in[9];
    const float* bih0r = (const float*)d_in[10];
    const float* bhh0r = (const float*)d_in[11];
    const float* Wih1  = (const float*)d_in[12];
    const float* Whh1  = (const float*)d_in[13];
    const float* bih1  = (const float*)d_in[14];
    const float* bhh1  = (const float*)d_in[15];
    const float* Wih1r = (const float*)d_in[16];
    const float* Whh1r = (const float*)d_in[17];
    const float* bih1r = (const float*)d_in[18];
    const float* bhh1r = (const float*)d_in[19];
    const float* mlpW  = (const float*)d_in[20];
    const float* mlpb  = (const float*)d_in[21];
    const float* outw  = (const float*)d_in[22];
    const float* outb  = (const float*)d_in[23];

    embed_k<<<LSEQ, DIN>>>(wi, pi, we, pe);
    zero_pub_k<<<512, 512>>>();

    // layer 0 input projections (both directions, one launch)
    gemm_tn<<<dim3(G4 / 64, LSEQ / 64, 2), 256>>>(
        0, 0, Wih0, bih0, bhh0, 3, Wih0r, bih0r, bhh0r, 4, LSEQ, G4, DIN);
    lstm_scan<<<64, 256>>>(Whh0, Whh0r, 6);

    // layer 1 input projections (A = pub1 layout)
    gemm_tn<<<dim3(G4 / 64, LSEQ / 64, 2), 256>>>(
        6, 1, Wih1, bih1, bhh1, 3, Wih1r, bih1r, bhh1r, 4, LSEQ, G4, 2 * HID);
    lstm_scan<<<64, 256>>>(Whh1, Whh1r, 7);

    // MLP projection (A = pub2 layout)
    gemm_tn<<<dim3(MDIM / 64, LSEQ / 64, 1), 256>>>(
        7, 1, mlpW, mlpb, nullptr, 5, mlpW, mlpb, nullptr, 5, LSEQ, MDIM, 2 * HID);
    // pairwise scores
    pair_scores<<<dim3(16, 16), 256>>>(outw, outb, (float*)d_out);
}

// round 8
// speedup vs baseline: 1.0649x; 1.0077x over previous
#include <cuda_runtime.h>
#include <cuda_bf16.h>

// Problem dims (fixed by the dataset)
#define LSEQ 512
#define DIN  320
#define HID  512
#define G4   2048   // 4*H
#define MDIM 512
#define NBLK 64     // blocks per direction
#define UPB  8      // hidden units per block

// ---------------- scratch (static device globals; no allocation) ----------
__device__ float g_x0 [LSEQ * DIN];        // embeddings
__device__ float g_zf [LSEQ * G4];         // input-projection, forward dir
__device__ float g_zb [LSEQ * G4];         // input-projection, backward dir
__device__ float g_mlp[LSEQ * MDIM];       // per-node MLP
// layer outputs in "publish line" layout: [dir][t][blk][32 words]
//   floats 0..7 = h chunk, word 8 = flag, rest pad (one 128B line)
__device__ __align__(128) float g_pub1[2 * LSEQ * NBLK * 32];
__device__ __align__(128) float g_pub2[2 * LSEQ * NBLK * 32];

__device__ __forceinline__ float* bufsel(int id) {
    switch (id) {
        case 0: return g_x0;
        case 3: return g_zf;
        case 4: return g_zb;
        case 5: return g_mlp;
        case 6: return g_pub1;
        default: return g_pub2;
    }
}

__device__ __forceinline__ float tanh_f(float x) {
    float a = fabsf(x);
    float e = __expf(-2.0f * a);
    float r = __fdividef(1.0f - e, 1.0f + e);
    return copysignf(r, x);
}

__device__ __forceinline__ void st_release_u32(unsigned int* p, unsigned int v) {
    asm volatile("st.release.gpu.global.u32 [%0], %1;" :: "l"(p), "r"(v) : "memory");
}
__device__ __forceinline__ unsigned int ld_acquire_u32(const unsigned int* p) {
    unsigned int v;
    asm volatile("ld.acquire.gpu.global.u32 %0, [%1];" : "=r"(v) : "l"(p) : "memory");
    return v;
}
__device__ __forceinline__ uint4 ldcg_v4(const uint4* p) {
    uint4 v;
    asm volatile("ld.global.cg.v4.u32 {%0,%1,%2,%3}, [%4];"
                 : "=r"(v.x), "=r"(v.y), "=r"(v.z), "=r"(v.w) : "l"(p) : "memory");
    return v;
}

// ---------------- embedding gather ----------------------------------------
__global__ void embed_k(const int* __restrict__ wi, const int* __restrict__ pi,
                        const float* __restrict__ we, const float* __restrict__ pe)
{
    int t = blockIdx.x;
    int d = threadIdx.x;             // 320 threads
    float v;
    if (d < 256) v = we[(size_t)wi[t] * 256 + d];
    else         v = pe[(size_t)pi[t] * 64 + (d - 256)];
    g_x0[t * DIN + d] = v;
}

// ---------------- pub reset (every replay, before the scans) --------------
__global__ void zero_pub_k()
{
    int idx = blockIdx.x * blockDim.x + threadIdx.x;   // 2048*512 = 1048576
    uint4 z = make_uint4(0u, 0u, 0u, 0u);
    if (idx < 524288) ((uint4*)g_pub1)[idx] = z;       // each buf: 524288 uint4
    else              ((uint4*)g_pub2)[idx - 524288] = z;
}

// ---------------- f32 GEMM:  C[M,N] = A[M,K] * B[N,K]^T + b1 + b2 ---------
// amode=0: A dense [M][K].  amode=1: A in pub-line layout (K=1024,
// col c -> pub[c>>9][row][(c&511)>>3][c&7]).
__global__ void __launch_bounds__(256) gemm_tn(
    int aid, int amode,
    const float* __restrict__ B0, const float* __restrict__ b1_0,
    const float* __restrict__ b2_0, int cid0,
    const float* __restrict__ B1, const float* __restrict__ b1_1,
    const float* __restrict__ b2_1, int cid1,
    int M, int N, int K)
{
    const float* A  = bufsel(aid);
    const float* B  = blockIdx.z ? B1   : B0;
    const float* b1 = blockIdx.z ? b1_1 : b1_0;
    const float* b2 = blockIdx.z ? b2_1 : b2_0;
    float*       C  = bufsel(blockIdx.z ? cid1 : cid0);

    __shared__ float As[16][65];
    __shared__ float Bs[16][65];

    const int tid = threadIdx.x;
    const int tx  = tid & 15;
    const int ty  = tid >> 4;
    const int m0  = blockIdx.y * 64;
    const int n0  = blockIdx.x * 64;

    const int lr = tid >> 2;
    const int lk = (tid & 3) * 4;

    const float* Ap = A + (size_t)(m0 + lr) * K + lk;           // amode=0 path
    const float* Aprow = A + (size_t)(m0 + lr) * (NBLK * 32);   // amode=1 path
    const float* Bp = B + (size_t)(n0 + lr) * K + lk;

    float acc[4][4] = {};

    for (int k0 = 0; k0 < K; k0 += 16) {
        float4 av;
        if (amode) {
            int c  = k0 + lk;                 // global column 0..1023
            int d  = c >> 9;                  // direction
            int cc = c & 511;
            av = *(const float4*)(Aprow + (size_t)d * (LSEQ * NBLK * 32)
                                  + (cc >> 3) * 32 + (cc & 7));
        } else {
            av = *(const float4*)(Ap + k0);
        }
        float4 bv = *(const float4*)(Bp + k0);
        __syncthreads();
        As[lk + 0][lr] = av.x; As[lk + 1][lr] = av.y;
        As[lk + 2][lr] = av.z; As[lk + 3][lr] = av.w;
        Bs[lk + 0][lr] = bv.x; Bs[lk + 1][lr] = bv.y;
        Bs[lk + 2][lr] = bv.z; Bs[lk + 3][lr] = bv.w;
        __syncthreads();
#pragma unroll
        for (int kk = 0; kk < 16; kk++) {
            float a[4], b[4];
#pragma unroll
            for (int i = 0; i < 4; i++) a[i] = As[kk][ty + 16 * i];
#pragma unroll
            for (int j = 0; j < 4; j++) b[j] = Bs[kk][tx + 16 * j];
#pragma unroll
            for (int i = 0; i < 4; i++)
#pragma unroll
                for (int j = 0; j < 4; j++)
                    acc[i][j] += a[i] * b[j];
        }
    }

#pragma unroll
    for (int j = 0; j < 4; j++) {
        int n = n0 + tx + 16 * j;
        float bb = 0.0f;
        if (b1) bb += b1[n];
        if (b2) bb += b2[n];
#pragma unroll
        for (int i = 0; i < 4; i++) {
            C[(size_t)(m0 + ty + 16 * i) * N + n] = acc[i][j] + bb;
        }
    }
}

// ---------------- persistent bidirectional LSTM scan ----------------------
// 128 blocks x 256 threads; blocks 0..63 fwd, 64..127 bwd. Each block owns 8
// hidden units (32 W_hh rows register-resident, packed f32x2).
// Publish: 8 h floats + flag(word 8) into ONE 128B per-step line
//   (h stores -> __syncwarp -> lane0 st.release flag).  [R5-proven]
// Consume: 63 pollers (warps 2-3) acquire-poll their peer's flag, then
//   ld.cg.v4 x2 the 32B h chunk into smem.
__global__ void __launch_bounds__(256, 1) lstm_scan(
    const float* __restrict__ whf, const float* __restrict__ whb, int outid)
{
    const int dir = blockIdx.x >> 6;     // 0 fwd, 1 bwd
    const int blk = blockIdx.x & 63;
    const int tid = threadIdx.x;
    const int row = tid >> 3;            // 0..31 local row
    const int sub = tid & 7;             // 8 threads per row
    const int grow = (row >> 3) * HID + blk * UPB + (row & 7);

    const float* zin = dir ? g_zb : g_zf;
    const float* Whh = dir ? whb : whf;
    float* pub = bufsel(outid) + (size_t)dir * LSEQ * NBLK * 32;

    // register-resident W_hh slice, packed as f32x2 (64 regs)
    unsigned long long wp[32];
    const unsigned long long* w2 =
        (const unsigned long long*)(Whh + (size_t)grow * HID);
#pragma unroll
    for (int k = 0; k < 32; k++) wp[k] = w2[sub + 8 * k];

    __shared__ __align__(16) float hs[HID];
    __shared__ float zs[32];
    hs[tid] = 0.0f; hs[tid + 256] = 0.0f;
    float c = 0.0f;                      // live only on lanes 0..7 of warp 0
    __syncthreads();

    for (int t = 0; t < LSEQ; t++) {
        const int ta = dir ? (LSEQ - 1 - t) : t;

        // prefetch input-projection term for this step (warp0, 32 lanes)
        float zp = 0.0f;
        if (tid < 32)
            zp = __ldg(zin + (size_t)ta * G4 + (tid >> 3) * HID
                       + blk * UPB + (tid & 7));

        // GEMV partial: 32 x (LDS.64 + FFMA2) per thread
        unsigned long long acc0 = 0ull, acc1 = 0ull;
#pragma unroll
        for (int k = 0; k < 32; k += 2) {
            unsigned long long h0 = *(const unsigned long long*)(hs + 2 * (sub + 8 * k));
            unsigned long long h1 = *(const unsigned long long*)(hs + 2 * (sub + 8 * (k + 1)));
            asm("fma.rn.f32x2 %0, %1, %2, %0;" : "+l"(acc0) : "l"(wp[k]),     "l"(h0));
            asm("fma.rn.f32x2 %0, %1, %2, %0;" : "+l"(acc1) : "l"(wp[k + 1]), "l"(h1));
        }
        float ax, ay, bx, by;
        asm("mov.b64 {%0,%1}, %2;" : "=f"(ax), "=f"(ay) : "l"(acc0));
        asm("mov.b64 {%0,%1}, %2;" : "=f"(bx), "=f"(by) : "l"(acc1));
        float acc = (ax + ay) + (bx + by);
        acc += __shfl_down_sync(0xffffffffu, acc, 4, 8);
        acc += __shfl_down_sync(0xffffffffu, acc, 2, 8);
        acc += __shfl_down_sync(0xffffffffu, acc, 1, 8);
        if (sub == 0) zs[row] = acc;
        __syncthreads();

        // gates: warp 0, one transcendental per lane, combine via shfl
        if (tid < 32) {
            const int gate = tid >> 3;               // 0=i 1=f 2=g 3=o
            float z = zp + zs[tid];
            float arg = (gate == 2) ? z : 0.5f * z;
            float tv = tanh_f(arg);
            float val = (gate == 2) ? tv : 0.5f + 0.5f * tv;   // sigm via tanh
            float fg = __shfl_sync(0xffffffffu, val, tid + 8);
            float gg = __shfl_sync(0xffffffffu, val, tid + 16);
            float og = __shfl_sync(0xffffffffu, val, tid + 24);
            float* line = pub + ((size_t)ta * NBLK + blk) * 32;
            if (tid < 8) {
                c = fg * c + val * gg;
                float h = og * tanh_f(c);
                line[tid] = h;                       // publish h word
                hs[blk * UPB + tid] = h;             // own chunk direct to smem
            }
            __syncwarp(0xffffffffu);
            if (tid == 0)
                st_release_u32((unsigned int*)(line + 8), 1u);
        }

        // consume h_t: 63 pollers (tid 64..126), one peer line each
        if (t < LSEQ - 1) {
            int pp = tid - 64;
            if (pp >= 0 && pp < 63) {
                int peer = pp + (pp >= blk ? 1 : 0);       // skip own block
                const float* line = pub + ((size_t)ta * NBLK + peer) * 32;
                const unsigned int* fp = (const unsigned int*)(line + 8);
                while (ld_acquire_u32(fp) == 0u) { }
                uint4 a = ldcg_v4((const uint4*)line);
                uint4 b = ldcg_v4((const uint4*)line + 1);
                uint4* hd = (uint4*)(hs + peer * UPB);
                hd[0] = a; hd[1] = b;
            }
        }
        __syncthreads();
    }
}

// ---------------- pairwise scores ------------------------------------------
__global__ void __launch_bounds__(256) pair_scores(
    const float* __restrict__ ow, const float* __restrict__ obp,
    float* __restrict__ out)
{
    __shared__ float miT[64][33];
    __shared__ float mjT[64][33];
    __shared__ float wch[64];

    const int tid = threadIdx.x;
    const int tx  = tid & 31;
    const int ty  = tid >> 5;            // 0..7
    const int i0  = blockIdx.y * 32;
    const int j0  = blockIdx.x * 32;

    float acc[4] = {0.f, 0.f, 0.f, 0.f};

    for (int mc = 0; mc < MDIM; mc += 64) {
        __syncthreads();
#pragma unroll
        for (int rep = 0; rep < 8; rep++) {
            int idx  = tid + rep * 256;
            int r    = idx >> 6;
            int cidx = idx & 63;
            miT[cidx][r] = g_mlp[(size_t)(i0 + r) * MDIM + mc + cidx];
            int jrow = j0 + r + 1;
            mjT[cidx][r] = (jrow < LSEQ)
                         ? g_mlp[(size_t)jrow * MDIM + mc + cidx] : 0.0f;
        }
        if (tid < 64) wch[tid] = ow[mc + tid];
        __syncthreads();

#pragma unroll 4
        for (int cc = 0; cc < 64; cc++) {
            float jv = mjT[cc][tx];
            float wv = wch[cc];
#pragma unroll
            for (int ii = 0; ii < 4; ii++) {
                float v = miT[cc][ty + 8 * ii] + jv;
                acc[ii] += tanh_f(v) * wv;
            }
        }
    }

    float ob = obp[0];
    int j = j0 + tx;
    if (j < LSEQ - 1) {
#pragma unroll
        for (int ii = 0; ii < 4; ii++) {
            int i = i0 + ty + 8 * ii;
            out[(size_t)i * (LSEQ - 1) + j] = acc[ii] + ob;
        }
    }
}

// ---------------- launch ----------------------------------------------------
extern "C" void kernel_launch(void* const* d_in, const int* in_sizes, int n_in,
                              void* d_out, int out_size)
{
    const int*   wi    = (const int*)  d_in[0];
    const int*   pi    = (const int*)  d_in[1];
    const float* we    = (const float*)d_in[2];
    const float* pe    = (const float*)d_in[3];
    const float* Wih0  = (const float*)d_in[4];
    const float* Whh0  = (const float*)d_in[5];
    const float* bih0  = (const float*)d_in[6];
    const float* bhh0  = (const float*)d_in[7];
    const float* Wih0r = (const float*)d_in[8];
    const float* Whh0r = (const float*)d_in[9];
    const float* bih0r = (const float*)d_in[10];
    const float* bhh0r = (const float*)d_in[11];
    const float* Wih1  = (const float*)d_in[12];
    const float* Whh1  = (const float*)d_in[13];
    const float* bih1  = (const float*)d_in[14];
    const float* bhh1  = (const float*)d_in[15];
    const float* Wih1r = (const float*)d_in[16];
    const float* Whh1r = (const float*)d_in[17];
    const float* bih1r = (const float*)d_in[18];
    const float* bhh1r = (const float*)d_in[19];
    const float* mlpW  = (const float*)d_in[20];
    const float* mlpb  = (const float*)d_in[21];
    const float* outw  = (const float*)d_in[22];
    const float* outb  = (const float*)d_in[23];

    embed_k<<<LSEQ, DIN>>>(wi, pi, we, pe);
    zero_pub_k<<<2048, 512>>>();

    // layer 0 input projections (both directions, one launch)
    gemm_tn<<<dim3(G4 / 64, LSEQ / 64, 2), 256>>>(
        0, 0, Wih0, bih0, bhh0, 3, Wih0r, bih0r, bhh0r, 4, LSEQ, G4, DIN);
    lstm_scan<<<128, 256>>>(Whh0, Whh0r, 6);

    // layer 1 input projections (A = pub1 layout)
    gemm_tn<<<dim3(G4 / 64, LSEQ / 64, 2), 256>>>(
        6, 1, Wih1, bih1, bhh1, 3, Wih1r, bih1r, bhh1r, 4, LSEQ, G4, 2 * HID);
    lstm_scan<<<128, 256>>>(Whh1, Whh1r, 7);

    // MLP projection (A = pub2 layout)
    gemm_tn<<<dim3(MDIM / 64, LSEQ / 64, 1), 256>>>(
        7, 1, mlpW, mlpb, nullptr, 5, mlpW, mlpb, nullptr, 5, LSEQ, MDIM, 2 * HID);
    // pairwise scores
    pair_scores<<<dim3(16, 16), 256>>>(outw, outb, (float*)d_out);
}